// round 10
// baseline (speedup 1.0000x reference)
#include <cuda_runtime.h>

// HardLinearAttention — algebraic collapse of P@Z@M@Z^T@Q@Z.
// d=1024, n=8192, Z is (2d+1, n+1) = (2049, 8193) float32.
//
//   v[j]  = sum_{k<8192} Z[j,k] * Z[2048,k]          (j < 1024)
//   r[k]  = sum_{j<1024} v[j] * (Z[1024+j,k] - Z[j,k])
//   out   = Z;  out[2048,k] += (alpha/8192) * r[k]

#define D       1024
#define NCOLS   8192
#define S       8193          // n+1 (row stride)
#define JCHUNKS 16
#define JPER    (D / JCHUNKS) // 64
#define CBLK    32            // column blocks for k1 (32*256 = 8192)

__device__ float g_v[D];
__device__ float g_vp[CBLK * D];      // v partials: [colblock][j]
__device__ float g_part[JCHUNKS * S];

// ---------------- kernel 1a: column-parallel v partials ------------------
// Same memory shape as k2 (the kernel that reaches ~6 TB/s): thread owns one
// column, iterates over rows; every iteration's load is independent. u[k] is
// held in a register for the whole kernel.
__global__ void __launch_bounds__(256) k_dot_cols(const float* __restrict__ Z) {
    const int cb  = blockIdx.x;                 // 0..31
    const int jc  = blockIdx.y;                 // 0..15
    const int tid = threadIdx.x;
    const int k   = cb * 256 + tid;             // 0..8191 (< NCOLS always)
    const int j0  = jc * 64;

    const float u_t = Z[(size_t)2048 * S + k];

    __shared__ float sp[64][8];
    const int lane = tid & 31;
    const int w    = tid >> 5;

    const float* __restrict__ zp = Z + (size_t)j0 * S + k;

    #pragma unroll 8
    for (int jj = 0; jj < 64; jj++) {
        float val = zp[(size_t)jj * S] * u_t;
        #pragma unroll
        for (int o = 16; o > 0; o >>= 1)
            val += __shfl_down_sync(0xffffffffu, val, o);
        if (lane == 0) sp[jj][w] = val;
    }
    __syncthreads();

    if (tid < 64) {
        float s = 0.f;
        #pragma unroll
        for (int w8 = 0; w8 < 8; w8++) s += sp[tid][w8];
        g_vp[cb * D + j0 + tid] = s;
    }
}

// ---------------- kernel 1b: fold column-block partials into v -----------
__global__ void __launch_bounds__(256) k_vred() {
    const int j = blockIdx.x * 256 + threadIdx.x;   // 0..1023
    float s = 0.f;
    #pragma unroll
    for (int cb = 0; cb < CBLK; cb++)
        s += g_vp[cb * D + j];
    g_v[j] = s;
}

// ---------------- kernel 2: copy rows 0..2047 + partial r accumulation ---
// grid = (ceil(S/256), JCHUNKS); each thread owns one column k.
// Unchanged from the 35.4us best (~6.1 TB/s effective).
__global__ void __launch_bounds__(256) k_copy_acc(const float* __restrict__ Z,
                                                  float* __restrict__ out) {
    const int jc = blockIdx.y;
    const int k  = blockIdx.x * 256 + threadIdx.x;

    __shared__ float vs[JPER];
    if (threadIdx.x < JPER) vs[threadIdx.x] = g_v[jc * JPER + threadIdx.x];
    __syncthreads();

    if (k >= S) return;

    const int j0 = jc * JPER;
    float acc = 0.f;
    #pragma unroll 8
    for (int jj = 0; jj < JPER; jj++) {
        const size_t ia = (size_t)(j0 + jj) * S + k;
        const size_t ib = (size_t)(j0 + jj + D) * S + k;
        const float a = Z[ia];
        const float b = Z[ib];
        out[ia] = a;
        out[ib] = b;
        acc += vs[jj] * (b - a);
    }
    g_part[(size_t)jc * S + k] = acc;
}

// ---------------- kernel 3: reduce partials, write final row 2048 --------
__global__ void __launch_bounds__(256) k_final(const float* __restrict__ Z,
                                               const float* __restrict__ alpha,
                                               float* __restrict__ out) {
    const int k = blockIdx.x * 256 + threadIdx.x;
    if (k >= S) return;
    float sum = 0.f;
    #pragma unroll
    for (int jc = 0; jc < JCHUNKS; jc++)
        sum += g_part[(size_t)jc * S + k];
    const float scale = alpha[0] / (float)NCOLS;
    out[(size_t)2048 * S + k] = Z[(size_t)2048 * S + k] + scale * sum;
}

extern "C" void kernel_launch(void* const* d_in, const int* in_sizes, int n_in,
                              void* d_out, int out_size) {
    const float* Z     = (const float*)d_in[0];
    const float* alpha = (const float*)d_in[1];
    float* out         = (float*)d_out;

    dim3 g1(CBLK, JCHUNKS);              // 32 x 16 = 512 blocks
    k_dot_cols<<<g1, 256>>>(Z);

    k_vred<<<D / 256, 256>>>();

    dim3 g2((S + 255) / 256, JCHUNKS);
    k_copy_acc<<<g2, 256>>>(Z, out);

    k_final<<<(S + 255) / 256, 256>>>(Z, alpha, out);
}

// round 12
// speedup vs baseline: 1.0874x; 1.0874x over previous
#include <cuda_runtime.h>

// HardLinearAttention — algebraic collapse of P@Z@M@Z^T@Q@Z.
// d=1024, n=8192, Z is (2d+1, n+1) = (2049, 8193) float32.
//
//   v[j]  = sum_{k<8192} Z[j,k] * Z[2048,k]          (j < 1024)
//   r[k]  = sum_{j<1024} v[j] * (Z[1024+j,k] - Z[j,k])
//   out   = Z;  out[2048,k] += (alpha/8192) * r[k]

#define D       1024
#define NCOLS   8192
#define S       8193          // n+1 (row stride)
#define JCHUNKS 16
#define JPER    (D / JCHUNKS) // 64
#define CHUNK   2048          // k1 pipeline chunk (floats)
#define NCHUNK  (NCOLS / CHUNK)

__device__ float g_v[D];
__device__ float g_part[JCHUNKS * S];

__device__ __forceinline__ unsigned smem_u32(const void* p) {
    return (unsigned)__cvta_generic_to_shared(p);
}
__device__ __forceinline__ void cp4(unsigned dst, const float* src) {
    asm volatile("cp.async.ca.shared.global [%0], [%1], 4;" :: "r"(dst), "l"(src));
}
__device__ __forceinline__ void cp16(unsigned dst, const float* src) {
    asm volatile("cp.async.ca.shared.global [%0], [%1], 16;" :: "r"(dst), "l"(src));
}
__device__ __forceinline__ void cp_commit() {
    asm volatile("cp.async.commit_group;");
}
template <int N>
__device__ __forceinline__ void cp_wait() {
    asm volatile("cp.async.wait_group %0;" :: "n"(N));
}

// ---------------- kernel 1: v via cp.async double-buffered pipeline ------
// Block b handles rows {b, b+512}. cp.async creates MLP without register
// liveness (fire-and-forget into smem) — the thing 4 rounds of LDG pragma
// games could not get out of ptxas (regs pinned at 32, MLP_eff~2, 3.0 TB/s).
__global__ void __launch_bounds__(256) k_compute_v(const float* __restrict__ Z) {
    __shared__ __align__(16) float sa[2][CHUNK];
    __shared__ __align__(16) float sb[2][CHUNK];
    __shared__ __align__(16) float su[2][CHUNK];

    const int b   = blockIdx.x;                 // 0..511
    const int tid = threadIdx.x;
    const float* __restrict__ ra = Z + (size_t)b * S;
    const float* __restrict__ rb = Z + (size_t)(b + 512) * S;
    const float* __restrict__ u  = Z + (size_t)2048 * S;   // 16B-aligned

    // issue chunk c into buffer nb
    auto issue = [&](int c, int nb) {
        const int k0 = c * CHUNK;
        const unsigned da = smem_u32(&sa[nb][0]);
        const unsigned db = smem_u32(&sb[nb][0]);
        const unsigned du = smem_u32(&su[nb][0]);
        #pragma unroll
        for (int s = 0; s < CHUNK / 256; s++) {             // 8 x 4B per row
            const int i = tid + 256 * s;
            cp4(da + 4u * i, ra + k0 + i);
            cp4(db + 4u * i, rb + k0 + i);
        }
        #pragma unroll
        for (int s = 0; s < CHUNK / (256 * 4); s++) {       // 2 x 16B for u
            const int i4 = tid + 256 * s;
            cp16(du + 16u * i4, u + k0 + 4 * i4);
        }
    };

    float acc0 = 0.f, acc1 = 0.f;

    issue(0, 0);
    cp_commit();

    for (int c = 0; c < NCHUNK; c++) {
        if (c + 1 < NCHUNK) {
            issue(c + 1, (c + 1) & 1);
            cp_commit();
            cp_wait<1>();                       // chunk c landed
        } else {
            cp_wait<0>();
        }
        __syncthreads();

        const int buf = c & 1;
        #pragma unroll
        for (int s = 0; s < CHUNK / (256 * 4); s++) {
            const int i4 = tid + 256 * s;
            const float4 u4 = ((const float4*)su[buf])[i4];
            const float4 a4 = ((const float4*)sa[buf])[i4];
            const float4 b4 = ((const float4*)sb[buf])[i4];
            acc0 += a4.x * u4.x + a4.y * u4.y + a4.z * u4.z + a4.w * u4.w;
            acc1 += b4.x * u4.x + b4.y * u4.y + b4.z * u4.z + b4.w * u4.w;
        }
        __syncthreads();                        // buffer reuse fence
    }

    // block reduce (two values)
    #pragma unroll
    for (int o = 16; o > 0; o >>= 1) {
        acc0 += __shfl_down_sync(0xffffffffu, acc0, o);
        acc1 += __shfl_down_sync(0xffffffffu, acc1, o);
    }
    __shared__ float s0[8], s1[8];
    const int lane = tid & 31;
    const int w    = tid >> 5;
    if (lane == 0) { s0[w] = acc0; s1[w] = acc1; }
    __syncthreads();
    if (w == 0) {
        acc0 = (lane < 8) ? s0[lane] : 0.f;
        acc1 = (lane < 8) ? s1[lane] : 0.f;
        #pragma unroll
        for (int o = 4; o > 0; o >>= 1) {
            acc0 += __shfl_down_sync(0xffffffffu, acc0, o);
            acc1 += __shfl_down_sync(0xffffffffu, acc1, o);
        }
        if (lane == 0) { g_v[b] = acc0; g_v[b + 512] = acc1; }
    }
}

// ---------------- kernel 2: copy rows 0..2047 + partial r accumulation ---
// Unchanged — measured ~6.9 TB/s effective, at the HBM roofline.
__global__ void __launch_bounds__(256) k_copy_acc(const float* __restrict__ Z,
                                                  float* __restrict__ out) {
    const int jc = blockIdx.y;
    const int k  = blockIdx.x * 256 + threadIdx.x;

    __shared__ float vs[JPER];
    if (threadIdx.x < JPER) vs[threadIdx.x] = g_v[jc * JPER + threadIdx.x];
    __syncthreads();

    if (k >= S) return;

    const int j0 = jc * JPER;
    float acc = 0.f;
    #pragma unroll 8
    for (int jj = 0; jj < JPER; jj++) {
        const size_t ia = (size_t)(j0 + jj) * S + k;
        const size_t ib = (size_t)(j0 + jj + D) * S + k;
        const float a = Z[ia];
        const float b = Z[ib];
        out[ia] = a;
        out[ib] = b;
        acc += vs[jj] * (b - a);
    }
    g_part[(size_t)jc * S + k] = acc;
}

// ---------------- kernel 3: reduce partials, write final row 2048 --------
// 4x wider than before: 129 blocks; 4 groups/block each sum 4 chunks,
// folded through smem. (Old version: grid=33, 4.4us, 127 GB/s.)
__global__ void __launch_bounds__(256) k_final(const float* __restrict__ Z,
                                               const float* __restrict__ alpha,
                                               float* __restrict__ out) {
    __shared__ float sp[4][64];
    const int g = threadIdx.x >> 6;             // chunk group 0..3
    const int c = threadIdx.x & 63;
    const int k = blockIdx.x * 64 + c;

    float sum = 0.f;
    if (k <= NCOLS) {
        #pragma unroll
        for (int q = 0; q < 4; q++)
            sum += g_part[(size_t)(4 * g + q) * S + k];
    }
    sp[g][c] = sum;
    __syncthreads();

    if (threadIdx.x < 64) {
        const int kk = blockIdx.x * 64 + threadIdx.x;
        if (kk <= NCOLS) {
            const float tot = sp[0][threadIdx.x] + sp[1][threadIdx.x]
                            + sp[2][threadIdx.x] + sp[3][threadIdx.x];
            const float scale = alpha[0] / (float)NCOLS;
            out[(size_t)2048 * S + kk] = Z[(size_t)2048 * S + kk] + scale * tot;
        }
    }
}

extern "C" void kernel_launch(void* const* d_in, const int* in_sizes, int n_in,
                              void* d_out, int out_size) {
    const float* Z     = (const float*)d_in[0];
    const float* alpha = (const float*)d_in[1];
    float* out         = (float*)d_out;

    k_compute_v<<<512, 256>>>(Z);

    dim3 g2((S + 255) / 256, JCHUNKS);
    k_copy_acc<<<g2, 256>>>(Z, out);

    k_final<<<(NCOLS + 64) / 64, 256>>>(Z, alpha, out);   // 129 blocks
}